// round 15
// baseline (speedup 1.0000x reference)
#include <cuda_runtime.h>

#define NX       1024
#define NTOP     5
#define THREADS  128
#define RPB      4      // rows per block (one warp per row)
#define EPT      32     // elements per lane
#define LOG2E    1.4426950408889634f

__device__ __forceinline__ float ex2f(float x) {
    float r; asm("ex2.approx.f32 %0, %1;" : "=f"(r) : "f"(x)); return r;
}
__device__ __forceinline__ float rcpf(float x) {
    float r; asm("rcp.approx.f32 %0, %1;" : "=f"(r) : "f"(x)); return r;
}

__global__ __launch_bounds__(THREADS, 6)
void lml_kernel(const float* __restrict__ x, float* __restrict__ y) {
    const int warp = threadIdx.x >> 5;
    const int lane = threadIdx.x & 31;
    const size_t row = (size_t)blockIdx.x * RPB + warp;

    const float4* xr = reinterpret_cast<const float4*>(x + row * NX);

    // ---- Load row: 8 coalesced float4 per lane (one HBM read) ----
    float xv[EPT];
    #pragma unroll
    for (int k = 0; k < 8; ++k) {
        float4 v = xr[lane + 32 * k];
        xv[4 * k + 0] = v.x; xv[4 * k + 1] = v.y;
        xv[4 * k + 2] = v.z; xv[4 * k + 3] = v.w;
    }

    // ---- Phase 1: E_j = e^{x_j} once (the only EX2 per element), full sum.
    // Far-field init in closed form: e^{nu0} = 5 / sum(E).  No lg2/ex2 on the
    // scalar path, no sampling noise; systematic error e0 = B/5 ~ 0.013
    // (B = sum sigma^2), worst-row ~0.06 — well inside Halley's basin.
    float S;
    {
        float S0 = 0.f, S1 = 0.f, S2 = 0.f, S3 = 0.f;
        #pragma unroll
        for (int j = 0; j < EPT; j += 4) {
            float e0 = ex2f(xv[j + 0] * LOG2E);
            float e1 = ex2f(xv[j + 1] * LOG2E);
            float e2 = ex2f(xv[j + 2] * LOG2E);
            float e3 = ex2f(xv[j + 3] * LOG2E);
            xv[j + 0] = e0; xv[j + 1] = e1;
            xv[j + 2] = e2; xv[j + 3] = e3;
            S0 += e0; S1 += e1; S2 += e2; S3 += e3;
        }
        S = (S0 + S1) + (S2 + S3);
        #pragma unroll
        for (int off = 16; off; off >>= 1)
            S += __shfl_xor_sync(0xffffffffu, S, off);
    }
    const float K = S * (1.0f / (float)NTOP);   // e^{-nu0} = S/5

    // ---- Phase 2: single pass, 1 MUFU per element.
    // sigma(x_j + nu0) = E_j / (E_j + K)  ->  FADD + RCP + FMUL.
    // Accumulate A,B,C (split accumulators); Halley step delta
    // (residual 0.42 e0^3 ~ 1e-6 typical, ~9e-5 worst row);
    // emit y = r + r(1-r)*delta*(1 + (0.5-r)*delta).
    {
        float A0 = 0.f, A1 = 0.f, B0 = 0.f, B1 = 0.f, C0 = 0.f, C1 = 0.f;
        #pragma unroll
        for (int j = 0; j < EPT; j += 2) {
            float ra = xv[j]     * rcpf(xv[j]     + K);
            float rb = xv[j + 1] * rcpf(xv[j + 1] + K);
            xv[j]     = ra;
            xv[j + 1] = rb;
            A0 += ra;                   A1 += rb;
            B0 = fmaf(ra, ra, B0);      B1 = fmaf(rb, rb, B1);
            C0 = fmaf(ra * ra, ra, C0); C1 = fmaf(rb * rb, rb, C1);
        }
        float A = A0 + A1, B = B0 + B1, C = C0 + C1;
        #pragma unroll
        for (int off = 16; off; off >>= 1) {
            A += __shfl_xor_sync(0xffffffffu, A, off);
            B += __shfl_xor_sync(0xffffffffu, B, off);
            C += __shfl_xor_sync(0xffffffffu, C, off);
        }
        float fv  = A - (float)NTOP;
        float fp  = A - B;                            // > 0
        float fpp = fmaf(2.0f, C, A) - 3.0f * B;
        float den = fmaf(2.0f, fp * fp, -fv * fpp);   // > 0 near root
        const float delta = -__fdividef(2.0f * fv * fp, den);  // lane-uniform
        #pragma unroll
        for (int j = 0; j < EPT; ++j) {
            float r = xv[j];
            float t = fmaf(-r, r, r);                       // r(1-r)
            float u = delta * fmaf(0.5f - r, delta, 1.0f);  // 2nd-order Taylor
            xv[j] = fmaf(t, u, r);
        }
    }

    float4* yr = reinterpret_cast<float4*>(y + row * NX);
    #pragma unroll
    for (int k = 0; k < 8; ++k)
        yr[lane + 32 * k] = make_float4(xv[4 * k + 0], xv[4 * k + 1],
                                        xv[4 * k + 2], xv[4 * k + 3]);
}

extern "C" void kernel_launch(void* const* d_in, const int* in_sizes, int n_in,
                              void* d_out, int out_size) {
    const float* x = (const float*)d_in[0];
    float* y = (float*)d_out;
    int rows = in_sizes[0] / NX;
    lml_kernel<<<rows / RPB, THREADS>>>(x, y);
}

// round 17
// speedup vs baseline: 1.0049x; 1.0049x over previous
#include <cuda_runtime.h>

#define NX       1024
#define NTOP     5
#define THREADS  128
#define RPB      4      // rows per block (one warp per row)
#define EPT      32     // elements per lane
#define LOG2E    1.4426950408889634f

__device__ __forceinline__ float ex2f(float x) {
    float r; asm("ex2.approx.f32 %0, %1;" : "=f"(r) : "f"(x)); return r;
}
__device__ __forceinline__ float rcpf(float x) {
    float r; asm("rcp.approx.f32 %0, %1;" : "=f"(r) : "f"(x)); return r;
}

__global__ __launch_bounds__(THREADS, 8)
void lml_kernel(const float* __restrict__ x, float* __restrict__ y) {
    const int warp = threadIdx.x >> 5;
    const int lane = threadIdx.x & 31;
    const size_t row = (size_t)blockIdx.x * RPB + warp;

    const float4* xr = reinterpret_cast<const float4*>(x + row * NX);

    // ---- Phase 1 fused into the load: E_j = e^{x_j} as each float4 arrives,
    // accumulate S = sum E.  Closed-form far-field init: e^{nu0} = 5/S
    // (systematic error e0 = ln(1+B/5) ~ 0.013, worst row ~0.06 — inside
    // Halley's basin).  xv holds E afterwards.
    float xv[EPT];
    float Sa = 0.f, Sb = 0.f;
    #pragma unroll
    for (int k = 0; k < 8; ++k) {
        float4 v = xr[lane + 32 * k];
        float e0 = ex2f(v.x * LOG2E);
        float e1 = ex2f(v.y * LOG2E);
        float e2 = ex2f(v.z * LOG2E);
        float e3 = ex2f(v.w * LOG2E);
        xv[4 * k + 0] = e0; xv[4 * k + 1] = e1;
        xv[4 * k + 2] = e2; xv[4 * k + 3] = e3;
        Sa += e0 + e2;
        Sb += e1 + e3;
    }
    float S = Sa + Sb;
    #pragma unroll
    for (int off = 16; off; off >>= 1)
        S += __shfl_xor_sync(0xffffffffu, S, off);
    const float K = S * (1.0f / (float)NTOP);   // e^{-nu0} = S/5

    // ---- Phase 2: one register sweep, 1 MUFU per element.
    // r_j = E_j / (E_j + K); accumulate A,B,C; Halley step delta;
    // emit y = r + r(1-r)*delta*(1 + (0.5-r)*delta)   (2nd-order Taylor).
    {
        float A = 0.f, B = 0.f, C = 0.f;
        #pragma unroll
        for (int j = 0; j < EPT; ++j) {
            float r = xv[j] * rcpf(xv[j] + K);
            xv[j] = r;
            A += r;
            B = fmaf(r, r, B);
            C = fmaf(r * r, r, C);
        }
        // Interleaved butterflies: the three chains are independent, so the
        // 26-cycle SHFL latencies overlap 3-wide (~130 cyc tail, not ~390).
        #pragma unroll
        for (int off = 16; off; off >>= 1) {
            float a = __shfl_xor_sync(0xffffffffu, A, off);
            float b = __shfl_xor_sync(0xffffffffu, B, off);
            float c = __shfl_xor_sync(0xffffffffu, C, off);
            A += a; B += b; C += c;
        }

        float fv  = A - (float)NTOP;
        float fp  = A - B;                            // > 0
        float fpp = fmaf(2.0f, C, A) - 3.0f * B;
        float den = fmaf(2.0f, fp * fp, -fv * fpp);   // > 0 near root
        const float delta = -__fdividef(2.0f * fv * fp, den);  // lane-uniform
        #pragma unroll
        for (int j = 0; j < EPT; ++j) {
            float r = xv[j];
            float t = fmaf(-r, r, r);                       // r(1-r)
            float u = delta * fmaf(0.5f - r, delta, 1.0f);  // 2nd-order Taylor
            xv[j] = fmaf(t, u, r);
        }
    }

    float4* yr = reinterpret_cast<float4*>(y + row * NX);
    #pragma unroll
    for (int k = 0; k < 8; ++k)
        yr[lane + 32 * k] = make_float4(xv[4 * k + 0], xv[4 * k + 1],
                                        xv[4 * k + 2], xv[4 * k + 3]);
}

extern "C" void kernel_launch(void* const* d_in, const int* in_sizes, int n_in,
                              void* d_out, int out_size) {
    const float* x = (const float*)d_in[0];
    float* y = (float*)d_out;
    int rows = in_sizes[0] / NX;
    lml_kernel<<<rows / RPB, THREADS>>>(x, y);
}